// round 16
// baseline (speedup 1.0000x reference)
#include <cuda_runtime.h>
#include <cstdint>

#define BB  256
#define LL  512
#define DD  64
#define NID 10000
#define TMAX 32          // smem table rows (counts beyond this take the direct path)

// dynamic smem layout (bytes):
//   [0      ,  8192) table  : 32x64 f32   (g(a) rows, a in [0, nrows))
//   [8192   , 10240) cs     : 512 u32 packed (src_cnt | dst_cnt<<16) per src pos
//   [10240  , 12288) cd     : 512 u32 per dst pos
//   [12288  , 52288) hist   : 10000 u32 (lo16 = count in src, hi16 = count in dst)
//   [52288  , 52544) w1s    : 64 f32
//   [52544  , 52800) b1s    : 64 f32
//   [52800  , 52804) maxc
#define SMEM_BYTES 52816

// Direct computation of g(a)[e..e+3] for the (never-in-practice) case a >= nrows.
// Reads W2 from global (L1/L2-hot).
__device__ __forceinline__ float4 g_direct(uint32_t a, int lane,
                                           const float* __restrict__ w1s,
                                           const float* __restrict__ b1s,
                                           const float* __restrict__ b2,
                                           const float* __restrict__ W2) {
    float4 s = ((const float4*)b2)[lane];
    const int e = lane * 4;
    for (int d = 0; d < DD; ++d) {
        float hv = fmaf((float)a, w1s[d], b1s[d]);
        hv = hv > 0.f ? hv : 0.f;
        s.x = fmaf(hv, __ldg(&W2[(e + 0) * DD + d]), s.x);
        s.y = fmaf(hv, __ldg(&W2[(e + 1) * DD + d]), s.y);
        s.z = fmaf(hv, __ldg(&W2[(e + 2) * DD + d]), s.z);
        s.w = fmaf(hv, __ldg(&W2[(e + 3) * DD + d]), s.w);
    }
    return s;
}

__global__ void __launch_bounds__(512, 2) fused_encode(
        const int* __restrict__ src,
        const int* __restrict__ dst,
        const float* __restrict__ W1,
        const float* __restrict__ b1,
        const float* __restrict__ W2,
        const float* __restrict__ b2,
        float* __restrict__ out) {
    extern __shared__ unsigned char sraw[];
    float*    table = (float*)(sraw);
    uint32_t* cs    = (uint32_t*)(sraw + 8192);
    uint32_t* cd    = (uint32_t*)(sraw + 10240);
    uint32_t* hist  = (uint32_t*)(sraw + 12288);
    float*    w1s   = (float*)(sraw + 52288);
    float*    b1s   = (float*)(sraw + 52544);
    uint32_t* maxc  = (uint32_t*)(sraw + 52800);

    const int t = threadIdx.x;
    const int b = blockIdx.x;

    // --- phase 0: zero histogram (128-bit), stage w1/b1, load ids ---
    const uint4 z = make_uint4(0u, 0u, 0u, 0u);
    #pragma unroll
    for (int i = t; i < NID / 4; i += 512) ((uint4*)hist)[i] = z;
    if (t < DD)            w1s[t]      = W1[t];
    else if (t < 2 * DD)   b1s[t - DD] = b1[t - DD];
    if (t == 0) *maxc = 0u;

    const int sid = src[b * LL + t];
    const int did = dst[b * LL + t];
    __syncthreads();

    // --- phase 1: packed dual histogram ---
    atomicAdd(&hist[sid], 1u);
    atomicAdd(&hist[did], 0x10000u);
    __syncthreads();

    // --- phase 2: gather per-position counts, find max count in this batch ---
    const uint32_t hs = sid ? hist[sid] : 0u;   // padding id 0 -> (0,0)
    const uint32_t hd = did ? hist[did] : 0u;
    cs[t] = hs;
    cd[t] = hd;
    uint32_t m = max(max(hs & 0xFFFFu, hs >> 16), max(hd & 0xFFFFu, hd >> 16));
    m = __reduce_max_sync(0xFFFFFFFFu, m);
    if ((t & 31) == 0) atomicMax(maxc, m);
    __syncthreads();

    const int nrows = min((int)(*maxc) + 1, TMAX);

    // --- phase 3: single-pass table build from global W2 (batched float4) ---
    for (int idx = t; idx < nrows * DD; idx += 512) {
        const int a = idx >> 6, e = idx & 63;
        const float fa = (float)a;
        float s = b2[e];
        const float4* w2r4 = (const float4*)(W2 + e * DD);
        #pragma unroll 4
        for (int j = 0; j < 16; ++j) {
            const float4 w4 = __ldg(&w2r4[j]);
            const int d = j * 4;
            const float h0 = fmaxf(fmaf(fa, w1s[d + 0], b1s[d + 0]), 0.f);
            const float h1 = fmaxf(fmaf(fa, w1s[d + 1], b1s[d + 1]), 0.f);
            const float h2 = fmaxf(fmaf(fa, w1s[d + 2], b1s[d + 2]), 0.f);
            const float h3 = fmaxf(fmaf(fa, w1s[d + 3], b1s[d + 3]), 0.f);
            s = fmaf(h0, w4.x, s);
            s = fmaf(h1, w4.y, s);
            s = fmaf(h2, w4.z, s);
            s = fmaf(h3, w4.w, s);
        }
        table[idx] = s;
    }
    __syncthreads();

    // --- phase 4: streamed, float4-coalesced output (identical to champion).
    // 16 lanes per 64-f row, 512 threads cover 32 rows/iter, 16 iters. ---
    const int lane = t & 15;
    const float4* T4 = (const float4*)table;
    float4* __restrict__ osrc = (float4*)(out + (size_t)b * LL * DD);
    float4* __restrict__ odst = (float4*)(out + (size_t)BB * LL * DD
                                              + (size_t)b * LL * DD);

    for (int r = (t >> 4); r < LL; r += 32) {
        uint32_t c = cs[r];
        uint32_t a0 = c & 0xFFFFu, a1 = c >> 16;
        float4 v0 = (a0 < (uint32_t)nrows) ? T4[a0 * 16 + lane]
                                           : g_direct(a0, lane, w1s, b1s, b2, W2);
        float4 v1 = (a1 < (uint32_t)nrows) ? T4[a1 * 16 + lane]
                                           : g_direct(a1, lane, w1s, b1s, b2, W2);
        float4 w;
        w.x = v0.x + v1.x; w.y = v0.y + v1.y;
        w.z = v0.z + v1.z; w.w = v0.w + v1.w;
        osrc[r * 16 + lane] = w;

        c = cd[r];
        a0 = c & 0xFFFFu; a1 = c >> 16;
        v0 = (a0 < (uint32_t)nrows) ? T4[a0 * 16 + lane]
                                    : g_direct(a0, lane, w1s, b1s, b2, W2);
        v1 = (a1 < (uint32_t)nrows) ? T4[a1 * 16 + lane]
                                    : g_direct(a1, lane, w1s, b1s, b2, W2);
        w.x = v0.x + v1.x; w.y = v0.y + v1.y;
        w.z = v0.z + v1.z; w.w = v0.w + v1.w;
        odst[r * 16 + lane] = w;
    }
}

extern "C" void kernel_launch(void* const* d_in, const int* in_sizes, int n_in,
                              void* d_out, int out_size) {
    const int*   src = (const int*)d_in[0];
    const int*   dst = (const int*)d_in[1];
    const float* W1  = (const float*)d_in[2];
    const float* b1  = (const float*)d_in[3];
    const float* W2  = (const float*)d_in[4];
    const float* b2  = (const float*)d_in[5];
    float* out = (float*)d_out;

    cudaFuncSetAttribute(fused_encode,
                         cudaFuncAttributeMaxDynamicSharedMemorySize, SMEM_BYTES);
    fused_encode<<<BB, 512, SMEM_BYTES>>>(src, dst, W1, b1, W2, b2, out);
}